// round 11
// baseline (speedup 1.0000x reference)
#include <cuda_runtime.h>
#include <math.h>

#define T 8192
#define D 4096
#define E 8
#define KSEL 2
#define SLOTS (T * KSEL)
#define NHB 64             // hist blocks
#define SPB (SLOTS / NHB)  // 256 slots per hist block
#define RSF 1024           // float4 per D-row
#define NQ (T / 4)         // 2048 token groups (4 tokens each)
#define SGRID 148

// Output layout (float32, concatenated in reference-return order)
#define OFF_XG  0
#define OFF_CNT 67108864ll   // 16384*4096
#define OFF_IDX 67108872ll
#define OFF_SC  67125256ll

// Scratch (no allocations allowed -> __device__ globals)
__device__ int   g_exp[SLOTS];
__device__ float g_prob[SLOTS];
__device__ int   g_pos[SLOTS];
__device__ int   g_bhist[NHB * E];
__device__ volatile int g_sync;  // rank kernel global barrier (self-resetting)
__device__ int   g_done;

// ---------------------------------------------------------------------------
// Kernel A: router scores + top-2 + softmax.
// FULL W (128KB) staged once in dynamic SMEM. 1024 threads = 32 warps.
// Warp PAIR (2a, 2a+1) shares a 4-token group; each warp covers half of D
// (16 coalesced 128B iterations). Token group q = (w>>1)*148 + blk over
// 2048 groups -> ~27.7 active warps/SM (2x R10 occupancy) with unchanged
// per-token LDS:x wavefront cost. Scalar acc (32 regs) + current-x (16)
// keeps regs <= 64; latency hidden by warp count, not prefetch depth.
// Cross-half combine via 4KB smem + one syncthreads.
// ---------------------------------------------------------------------------
extern __shared__ float4 Ws[];   // [e * 1024 + i], 128KB

__global__ void __launch_bounds__(1024, 1) router_scores_kernel(
    const float* __restrict__ x, const float* __restrict__ W)
{
    __shared__ float comb[32][32];   // [warp][lane] reduced partials

    const int tid  = threadIdx.x;
    const int w    = tid >> 5;
    const int lane = tid & 31;

    const float4* __restrict__ x4 = (const float4*)x;
    const float4* __restrict__ w4 = (const float4*)W;

    // stage full W: 8192 float4, 8 per thread, coalesced
#pragma unroll
    for (int k = 0; k < 8; k++) {
        const int idx = tid + k * 1024;
        Ws[idx] = w4[idx];
    }
    __syncthreads();

    const int h = w & 1;                       // D-half
    const int q = (w >> 1) * SGRID + blockIdx.x;  // token group
    const bool active = (q < NQ);
    const int t0 = q * 4;

    if (active) {
        const float4* __restrict__ xr =
            x4 + (size_t)t0 * RSF + h * 512;   // this warp's half-row base

        float acc[4][E];
#pragma unroll
        for (int j = 0; j < 4; j++)
#pragma unroll
            for (int e = 0; e < E; e++) acc[j][e] = 0.f;

#pragma unroll 2
        for (int it = 0; it < 16; it++) {
            const int i = it * 32 + lane;      // within half (0..511)
            float4 xv0 = xr[i];
            float4 xv1 = xr[RSF + i];
            float4 xv2 = xr[2 * RSF + i];
            float4 xv3 = xr[3 * RSF + i];
#pragma unroll
            for (int e = 0; e < E; e++) {
                float4 wv = Ws[e * RSF + h * 512 + i];
                acc[0][e] += xv0.x * wv.x + xv0.y * wv.y + xv0.z * wv.z + xv0.w * wv.w;
                acc[1][e] += xv1.x * wv.x + xv1.y * wv.y + xv1.z * wv.z + xv1.w * wv.w;
                acc[2][e] += xv2.x * wv.x + xv2.y * wv.y + xv2.z * wv.z + xv2.w * wv.w;
                acc[3][e] += xv3.x * wv.x + xv3.y * wv.y + xv3.z * wv.z + xv3.w * wv.w;
            }
        }

        // warp tree-reduce: every lane ends with all 32 totals
#pragma unroll
        for (int off = 16; off > 0; off >>= 1) {
#pragma unroll
            for (int j = 0; j < 4; j++)
#pragma unroll
                for (int e = 0; e < E; e++)
                    acc[j][e] += __shfl_xor_sync(0xffffffffu, acc[j][e], off);
        }

        // lane (j*8+e) stashes its designated partial
#pragma unroll
        for (int j = 0; j < 4; j++)
#pragma unroll
            for (int e = 0; e < E; e++)
                if (lane == j * 8 + e) comb[w][lane] = acc[j][e];
    }
    __syncthreads();

    if (active && h == 0) {
        // sum the two D-halves; lane l holds score(token j=l>>3, expert e=l&7)
        float v = comb[w][lane] + comb[w + 1][lane];

        // lane j (<4) gathers the 8 scores of its token
        float sv[E];
#pragma unroll
        for (int e = 0; e < E; e++)
            sv[e] = __shfl_sync(0xffffffffu, v, ((lane & 3) << 3) + e);

        if (lane < 4) {
            const int t = t0 + lane;
            // stable top-2 (first occurrence wins ties, matching jax.lax.top_k)
            float b0 = -3.4e38f, b1 = -3.4e38f;
            int i0 = 0, i1 = 0;
#pragma unroll
            for (int e = 0; e < E; e++) {
                float vv = sv[e];
                if (vv > b0) { b1 = b0; i1 = i0; b0 = vv; i0 = e; }
                else if (vv > b1) { b1 = vv; i1 = e; }
            }
            float ex = expf(b1 - b0);
            float inv = 1.f / (1.f + ex);
            ((int2*)g_exp)[t]    = make_int2(i0, i1);
            ((float2*)g_prob)[t] = make_float2(inv, ex * inv);
        }
    }
}

// ---------------------------------------------------------------------------
// Packed per-expert counters: 8 experts x 8-bit fields across two uints.
// ---------------------------------------------------------------------------
__device__ __forceinline__ void packAdd(int e, unsigned& lo, unsigned& hi) {
    if (e < 4) lo += 1u << (8 * e);
    else       hi += 1u << (8 * (e - 4));
}
__device__ __forceinline__ int fieldOf(unsigned lo, unsigned hi, int e) {
    unsigned v = (e < 4) ? lo : hi;
    return (int)((v >> (8 * (e & 3))) & 0xffu);
}

// ---------------------------------------------------------------------------
// Kernel B: fused rank (hist + global barrier + finalize), 64 blocks x 256.
// All 64 blocks co-resident (64 < 148 SMs) -> spin barrier safe.
// Counters self-reset for graph replay determinism.
// ---------------------------------------------------------------------------
__global__ void __launch_bounds__(SPB) rank_kernel(float* __restrict__ out)
{
    __shared__ unsigned wlo[8], whi[8];
    __shared__ int offE[E], totE[E], baseE[E];

    const int b    = blockIdx.x;
    const int tid  = threadIdx.x;
    const int wid  = tid >> 5;
    const int lane = tid & 31;
    const int slot = b * SPB + tid;

    // ---- phase 1: local stable rank + per-block histogram ----
    const int e = g_exp[slot];
    unsigned lo = 0, hi = 0;
    packAdd(e, lo, hi);
    const unsigned mlo = lo, mhi = hi;

#pragma unroll
    for (int off = 1; off < 32; off <<= 1) {
        unsigned vlo = __shfl_up_sync(0xffffffffu, lo, off);
        unsigned vhi = __shfl_up_sync(0xffffffffu, hi, off);
        if (lane >= off) { lo += vlo; hi += vhi; }
    }
    if (lane == 31) { wlo[wid] = lo; whi[wid] = hi; }
    __syncthreads();

    unsigned plo = 0, phi = 0;
#pragma unroll
    for (int w2 = 0; w2 < 8; w2++)
        if (w2 < wid) { plo += wlo[w2]; phi += whi[w2]; }

    const int lrank = fieldOf(plo + lo - mlo, phi + hi - mhi, e);

    if (tid < E) {
        unsigned tlo = 0, thi = 0;
#pragma unroll
        for (int w2 = 0; w2 < 8; w2++) { tlo += wlo[w2]; thi += whi[w2]; }
        g_bhist[b * E + tid] = fieldOf(tlo, thi, tid);
    }

    // ---- global barrier across the 64 blocks ----
    __threadfence();
    __syncthreads();
    if (tid == 0) atomicAdd((int*)&g_sync, 1);
    if (tid == 0) while (g_sync < NHB) { }
    __syncthreads();
    __threadfence();

    // ---- phase 2: finalize ----
    if (tid < E) {
        int off = 0, tot = 0;
#pragma unroll
        for (int bb = 0; bb < NHB; bb++) {
            int h = g_bhist[bb * E + tid];
            if (bb < b) off += h;
            tot += h;
        }
        offE[tid] = off; totE[tid] = tot;
    }
    __syncthreads();
    if (tid == 0) {
        int s = 0;
#pragma unroll
        for (int ee = 0; ee < E; ee++) { baseE[ee] = s; s += totE[ee]; }
    }
    __syncthreads();

    const int pos = baseE[e] + offE[e] + lrank;
    g_pos[slot] = pos;
    out[OFF_IDX + pos] = (float)(slot >> 1);   // scatter_indices
    out[OFF_SC  + pos] = g_prob[slot];         // scores_sorted

    if (b == 0 && tid < E) out[OFF_CNT + tid] = (float)totE[tid];

    // ---- self-reset for next graph replay ----
    __syncthreads();
    if (tid == 0) {
        int d = atomicAdd(&g_done, 1);
        if (d == NHB - 1) { g_sync = 0; g_done = 0; }
    }
}

// ---------------------------------------------------------------------------
// Kernel C: scatter copy — read each token row once, write 2 destination rows.
// ---------------------------------------------------------------------------
__global__ void __launch_bounds__(256) scatter_kernel(
    const float* __restrict__ x, float* __restrict__ out)
{
    const int t = blockIdx.x;
    const int p0 = g_pos[2 * t];
    const int p1 = g_pos[2 * t + 1];
    const float4* __restrict__ src = (const float4*)x + (size_t)t * 1024;
    float4* __restrict__ d0 = (float4*)(out + OFF_XG) + (size_t)p0 * 1024;
    float4* __restrict__ d1 = (float4*)(out + OFF_XG) + (size_t)p1 * 1024;

    const int i = threadIdx.x;
    float4 v0 = src[i];
    float4 v1 = src[i + 256];
    float4 v2 = src[i + 512];
    float4 v3 = src[i + 768];
    __stcs(d0 + i,       v0);
    __stcs(d0 + i + 256, v1);
    __stcs(d0 + i + 512, v2);
    __stcs(d0 + i + 768, v3);
    __stcs(d1 + i,       v0);
    __stcs(d1 + i + 256, v1);
    __stcs(d1 + i + 512, v2);
    __stcs(d1 + i + 768, v3);
}

extern "C" void kernel_launch(void* const* d_in, const int* in_sizes, int n_in,
                              void* d_out, int out_size)
{
    const float* x = (const float*)d_in[0];
    const float* W = (const float*)d_in[1];
    if (n_in >= 2 && in_sizes[0] == E * D && in_sizes[1] == (int)((size_t)T * D)) {
        const float* tmp = x; x = W; W = tmp;
    }
    float* out = (float*)d_out;

    static int smem_set = 0;
    if (!smem_set) {
        cudaFuncSetAttribute(router_scores_kernel,
                             cudaFuncAttributeMaxDynamicSharedMemorySize,
                             E * D * (int)sizeof(float));
        smem_set = 1;
    }

    router_scores_kernel<<<SGRID, 1024, E * D * sizeof(float)>>>(x, W);
    rank_kernel<<<NHB, SPB>>>(out);
    scatter_kernel<<<T, 256>>>(x, out);
}

// round 13
// speedup vs baseline: 1.0864x; 1.0864x over previous
#include <cuda_runtime.h>
#include <math.h>

#define T 8192
#define D 4096
#define E 8
#define KSEL 2
#define SLOTS (T * KSEL)
#define NHB 64             // hist blocks
#define SPB (SLOTS / NHB)  // 256 slots per hist block
#define RSF 1024           // float4 per D-row
#define NG4 (T / 4)        // 2048 warp-tasks (4 tokens each)
#define SGRID 148

// Output layout (float32, concatenated in reference-return order)
#define OFF_XG  0
#define OFF_CNT 67108864ll   // 16384*4096
#define OFF_IDX 67108872ll
#define OFF_SC  67125256ll

// Scratch (no allocations allowed -> __device__ globals)
__device__ int   g_exp[SLOTS];
__device__ float g_prob[SLOTS];
__device__ int   g_pos[SLOTS];
__device__ int   g_bhist[NHB * E];
__device__ volatile int g_sync;  // rank kernel global barrier (self-resetting)
__device__ int   g_done;

// L2 evict_last access policy (created once per thread)
__device__ __forceinline__ unsigned long long mk_policy_el() {
    unsigned long long p;
    asm("createpolicy.fractional.L2::evict_last.b64 %0, 1.0;" : "=l"(p));
    return p;
}
// float4 global load with cache_hint policy: x lines survive in L2
__device__ __forceinline__ float4 ldg_el(const float4* p, unsigned long long pol) {
    float4 v;
    asm("ld.global.L2::cache_hint.v4.f32 {%0,%1,%2,%3}, [%4], %5;"
        : "=f"(v.x), "=f"(v.y), "=f"(v.z), "=f"(v.w) : "l"(p), "l"(pol));
    return v;
}

// ---------------------------------------------------------------------------
// Kernel A: router scores + top-2 + softmax.  (R10 shape — best measured.)
// FULL W (128KB) staged once in dynamic SMEM -> barrier-free mainloop.
// grid=148, 512 threads = 16 warps. 4 tokens/warp, task g = w*148 + blk
// over 2048 tasks. Scalar fp32 acc + 2-deep rolling x prefetch.
// x loads use an L2 evict_last policy so x stays L2-resident for scatter.
// ---------------------------------------------------------------------------
extern __shared__ float4 Ws[];   // [e * 1024 + i], 128KB

__global__ void __launch_bounds__(512, 1) router_scores_kernel(
    const float* __restrict__ x, const float* __restrict__ W)
{
    const int tid  = threadIdx.x;
    const int w    = tid >> 5;
    const int lane = tid & 31;

    const float4* __restrict__ x4 = (const float4*)x;
    const float4* __restrict__ w4 = (const float4*)W;

    // stage full W: 8192 float4, 16 per thread, coalesced
#pragma unroll
    for (int k = 0; k < 16; k++) {
        const int idx = tid + k * 512;
        Ws[idx] = w4[idx];
    }
    __syncthreads();

    const int g = w * SGRID + blockIdx.x;
    if (g >= NG4) return;
    const int t0 = g * 4;

    const unsigned long long pol = mk_policy_el();

    const float4* __restrict__ xr0 = x4 + (size_t)t0 * RSF;
    const float4* __restrict__ xr1 = xr0 + RSF;
    const float4* __restrict__ xr2 = xr0 + 2 * RSF;
    const float4* __restrict__ xr3 = xr0 + 3 * RSF;

    float acc[4][E];
#pragma unroll
    for (int j = 0; j < 4; j++)
#pragma unroll
        for (int e = 0; e < E; e++) acc[j][e] = 0.f;

    // rolling buffers: A holds even iterations, B odd; prefetch depth 2
    float4 A0 = ldg_el(xr0 + lane, pol),      A1 = ldg_el(xr1 + lane, pol),
           A2 = ldg_el(xr2 + lane, pol),      A3 = ldg_el(xr3 + lane, pol);
    float4 B0 = ldg_el(xr0 + 32 + lane, pol), B1 = ldg_el(xr1 + 32 + lane, pol),
           B2 = ldg_el(xr2 + 32 + lane, pol), B3 = ldg_el(xr3 + 32 + lane, pol);

#pragma unroll 2
    for (int k = 0; k < 16; k++) {
        // ---- even iteration 2k (buffer A) ----
        {
            const int i = 2 * k * 32 + lane;
            float4 xa0 = A0, xa1 = A1, xa2 = A2, xa3 = A3;
            if (2 * k + 2 < 32) {
                const int ni = (2 * k + 2) * 32 + lane;
                A0 = ldg_el(xr0 + ni, pol); A1 = ldg_el(xr1 + ni, pol);
                A2 = ldg_el(xr2 + ni, pol); A3 = ldg_el(xr3 + ni, pol);
            }
#pragma unroll
            for (int e = 0; e < E; e++) {
                float4 wv = Ws[e * RSF + i];
                acc[0][e] += xa0.x * wv.x + xa0.y * wv.y + xa0.z * wv.z + xa0.w * wv.w;
                acc[1][e] += xa1.x * wv.x + xa1.y * wv.y + xa1.z * wv.z + xa1.w * wv.w;
                acc[2][e] += xa2.x * wv.x + xa2.y * wv.y + xa2.z * wv.z + xa2.w * wv.w;
                acc[3][e] += xa3.x * wv.x + xa3.y * wv.y + xa3.z * wv.z + xa3.w * wv.w;
            }
        }
        // ---- odd iteration 2k+1 (buffer B) ----
        {
            const int i = (2 * k + 1) * 32 + lane;
            float4 xb0 = B0, xb1 = B1, xb2 = B2, xb3 = B3;
            if (2 * k + 3 < 32) {
                const int ni = (2 * k + 3) * 32 + lane;
                B0 = ldg_el(xr0 + ni, pol); B1 = ldg_el(xr1 + ni, pol);
                B2 = ldg_el(xr2 + ni, pol); B3 = ldg_el(xr3 + ni, pol);
            }
#pragma unroll
            for (int e = 0; e < E; e++) {
                float4 wv = Ws[e * RSF + i];
                acc[0][e] += xb0.x * wv.x + xb0.y * wv.y + xb0.z * wv.z + xb0.w * wv.w;
                acc[1][e] += xb1.x * wv.x + xb1.y * wv.y + xb1.z * wv.z + xb1.w * wv.w;
                acc[2][e] += xb2.x * wv.x + xb2.y * wv.y + xb2.z * wv.z + xb2.w * wv.w;
                acc[3][e] += xb3.x * wv.x + xb3.y * wv.y + xb3.z * wv.z + xb3.w * wv.w;
            }
        }
    }

    // warp tree-reduce 32 scalars
#pragma unroll
    for (int off = 16; off > 0; off >>= 1) {
#pragma unroll
        for (int j = 0; j < 4; j++)
#pragma unroll
            for (int e = 0; e < E; e++)
                acc[j][e] += __shfl_xor_sync(0xffffffffu, acc[j][e], off);
    }

    // lanes 0..3 finalize token t0+lane
#pragma unroll
    for (int j = 0; j < 4; j++) {
        if (lane == j) {
            const int t = t0 + j;
            // stable top-2 (first occurrence wins ties, matching jax.lax.top_k)
            float b0 = -3.4e38f, b1 = -3.4e38f;
            int i0 = 0, i1 = 0;
#pragma unroll
            for (int e = 0; e < E; e++) {
                float v = acc[j][e];
                if (v > b0) { b1 = b0; i1 = i0; b0 = v; i0 = e; }
                else if (v > b1) { b1 = v; i1 = e; }
            }
            float ex = expf(b1 - b0);
            float inv = 1.f / (1.f + ex);
            ((int2*)g_exp)[t]    = make_int2(i0, i1);
            ((float2*)g_prob)[t] = make_float2(inv, ex * inv);
        }
    }
}

// ---------------------------------------------------------------------------
// Packed per-expert counters: 8 experts x 8-bit fields across two uints.
// ---------------------------------------------------------------------------
__device__ __forceinline__ void packAdd(int e, unsigned& lo, unsigned& hi) {
    if (e < 4) lo += 1u << (8 * e);
    else       hi += 1u << (8 * (e - 4));
}
__device__ __forceinline__ int fieldOf(unsigned lo, unsigned hi, int e) {
    unsigned v = (e < 4) ? lo : hi;
    return (int)((v >> (8 * (e & 3))) & 0xffu);
}

// ---------------------------------------------------------------------------
// Kernel B: fused rank (hist + global barrier + finalize), 64 blocks x 256.
// All 64 blocks co-resident (64 < 148 SMs) -> spin barrier safe.
// Counters self-reset for graph replay determinism.
// ---------------------------------------------------------------------------
__global__ void __launch_bounds__(SPB) rank_kernel(float* __restrict__ out)
{
    __shared__ unsigned wlo[8], whi[8];
    __shared__ int offE[E], totE[E], baseE[E];

    const int b    = blockIdx.x;
    const int tid  = threadIdx.x;
    const int wid  = tid >> 5;
    const int lane = tid & 31;
    const int slot = b * SPB + tid;

    // ---- phase 1: local stable rank + per-block histogram ----
    const int e = g_exp[slot];
    unsigned lo = 0, hi = 0;
    packAdd(e, lo, hi);
    const unsigned mlo = lo, mhi = hi;

#pragma unroll
    for (int off = 1; off < 32; off <<= 1) {
        unsigned vlo = __shfl_up_sync(0xffffffffu, lo, off);
        unsigned vhi = __shfl_up_sync(0xffffffffu, hi, off);
        if (lane >= off) { lo += vlo; hi += vhi; }
    }
    if (lane == 31) { wlo[wid] = lo; whi[wid] = hi; }
    __syncthreads();

    unsigned plo = 0, phi = 0;
#pragma unroll
    for (int w2 = 0; w2 < 8; w2++)
        if (w2 < wid) { plo += wlo[w2]; phi += whi[w2]; }

    const int lrank = fieldOf(plo + lo - mlo, phi + hi - mhi, e);

    if (tid < E) {
        unsigned tlo = 0, thi = 0;
#pragma unroll
        for (int w2 = 0; w2 < 8; w2++) { tlo += wlo[w2]; thi += whi[w2]; }
        g_bhist[b * E + tid] = fieldOf(tlo, thi, tid);
    }

    // ---- global barrier across the 64 blocks ----
    __threadfence();
    __syncthreads();
    if (tid == 0) atomicAdd((int*)&g_sync, 1);
    if (tid == 0) while (g_sync < NHB) { }
    __syncthreads();
    __threadfence();

    // ---- phase 2: finalize ----
    if (tid < E) {
        int off = 0, tot = 0;
#pragma unroll
        for (int bb = 0; bb < NHB; bb++) {
            int h = g_bhist[bb * E + tid];
            if (bb < b) off += h;
            tot += h;
        }
        offE[tid] = off; totE[tid] = tot;
    }
    __syncthreads();
    if (tid == 0) {
        int s = 0;
#pragma unroll
        for (int ee = 0; ee < E; ee++) { baseE[ee] = s; s += totE[ee]; }
    }
    __syncthreads();

    const int pos = baseE[e] + offE[e] + lrank;
    g_pos[slot] = pos;
    out[OFF_IDX + pos] = (float)(slot >> 1);   // scatter_indices
    out[OFF_SC  + pos] = g_prob[slot];         // scores_sorted

    if (b == 0 && tid < E) out[OFF_CNT + tid] = (float)totE[tid];

    // ---- self-reset for next graph replay ----
    __syncthreads();
    if (tid == 0) {
        int d = atomicAdd(&g_done, 1);
        if (d == NHB - 1) { g_sync = 0; g_done = 0; }
    }
}

// ---------------------------------------------------------------------------
// Kernel C: scatter copy — read each token row once, write 2 destination rows.
// Reads are last-use (__ldcs, evict-first); writes are streaming (__stcs)
// so the 268MB write stream victimizes itself in L2, not the x residue.
// ---------------------------------------------------------------------------
__global__ void __launch_bounds__(256) scatter_kernel(
    const float* __restrict__ x, float* __restrict__ out)
{
    const int t = blockIdx.x;
    const int p0 = g_pos[2 * t];
    const int p1 = g_pos[2 * t + 1];
    const float4* __restrict__ src = (const float4*)x + (size_t)t * 1024;
    float4* __restrict__ d0 = (float4*)(out + OFF_XG) + (size_t)p0 * 1024;
    float4* __restrict__ d1 = (float4*)(out + OFF_XG) + (size_t)p1 * 1024;

    const int i = threadIdx.x;
    float4 v0 = __ldcs(src + i);
    float4 v1 = __ldcs(src + i + 256);
    float4 v2 = __ldcs(src + i + 512);
    float4 v3 = __ldcs(src + i + 768);
    __stcs(d0 + i,       v0);
    __stcs(d0 + i + 256, v1);
    __stcs(d0 + i + 512, v2);
    __stcs(d0 + i + 768, v3);
    __stcs(d1 + i,       v0);
    __stcs(d1 + i + 256, v1);
    __stcs(d1 + i + 512, v2);
    __stcs(d1 + i + 768, v3);
}

extern "C" void kernel_launch(void* const* d_in, const int* in_sizes, int n_in,
                              void* d_out, int out_size)
{
    const float* x = (const float*)d_in[0];
    const float* W = (const float*)d_in[1];
    if (n_in >= 2 && in_sizes[0] == E * D && in_sizes[1] == (int)((size_t)T * D)) {
        const float* tmp = x; x = W; W = tmp;
    }
    float* out = (float*)d_out;

    static int smem_set = 0;
    if (!smem_set) {
        cudaFuncSetAttribute(router_scores_kernel,
                             cudaFuncAttributeMaxDynamicSharedMemorySize,
                             E * D * (int)sizeof(float));
        smem_set = 1;
    }

    router_scores_kernel<<<SGRID, 512, E * D * sizeof(float)>>>(x, W);
    rank_kernel<<<NHB, SPB>>>(out);
    scatter_kernel<<<T, 256>>>(x, out);
}

// round 14
// speedup vs baseline: 1.0882x; 1.0017x over previous
#include <cuda_runtime.h>
#include <math.h>

#define T 8192
#define D 4096
#define E 8
#define KSEL 2
#define SLOTS (T * KSEL)
#define NHB 64             // hist blocks
#define SPB (SLOTS / NHB)  // 256 slots per hist block
#define NG4 (T / 4)        // 2048 warp-tasks (4 tokens each)
#define SGRID 148

// Output layout (float32, concatenated in reference-return order)
#define OFF_XG  0
#define OFF_CNT 67108864ll   // 16384*4096
#define OFF_IDX 67108872ll
#define OFF_SC  67125256ll

// Scratch (no allocations allowed -> __device__ globals)
__device__ int   g_exp[SLOTS];
__device__ float g_prob[SLOTS];
__device__ int   g_pos[SLOTS];
__device__ int   g_bhist[NHB * E];
__device__ volatile int g_sync;  // rank kernel global barrier (self-resetting)
__device__ int   g_done;

// L2 evict_last access policy (created once per thread)
__device__ __forceinline__ unsigned long long mk_policy_el() {
    unsigned long long p;
    asm("createpolicy.fractional.L2::evict_last.b64 %0, 1.0;" : "=l"(p));
    return p;
}
// 256-bit global load (8 floats per lane = 1KB contiguous DRAM burst per warp)
__device__ __forceinline__ void ldg256_el(const float* p, unsigned long long pol,
                                          unsigned* v) {
    asm("ld.global.L2::cache_hint.v8.b32 {%0,%1,%2,%3,%4,%5,%6,%7}, [%8], %9;"
        : "=r"(v[0]), "=r"(v[1]), "=r"(v[2]), "=r"(v[3]),
          "=r"(v[4]), "=r"(v[5]), "=r"(v[6]), "=r"(v[7])
        : "l"(p), "l"(pol));
}
#define F(u) __uint_as_float(u)

// ---------------------------------------------------------------------------
// Kernel A: router scores + top-2 + softmax.
// R10 shape: grid=148, 512 threads = 16 warps, 4 tokens/warp, task
// g = w*148 + blk over 2048 tasks. FULL W (128KB) in SMEM.
// NEW: x read via 256-bit loads -> each warp pulls 1KB CONTIGUOUS per row
// per instruction (vs 128B) for DRAM page locality. 16 iterations of
// 256 floats/row; depth-1 register prefetch.
// W smem uses a bit-permuted layout so each lane's matching W float4 pair
// is at lane-consecutive addresses (conflict-free LDS.128).
// ---------------------------------------------------------------------------
extern __shared__ float4 Ws[];   // permuted [e][it][p][lane], 128KB

__global__ void __launch_bounds__(512, 1) router_scores_kernel(
    const float* __restrict__ x, const float* __restrict__ W)
{
    const int tid  = threadIdx.x;
    const int w    = tid >> 5;
    const int lane = tid & 31;

    const float4* __restrict__ w4 = (const float4*)W;

    // stage full W with permutation: linear float4 index m -> slot
    // (m & ~63) | ((m & 1) << 5) | ((m >> 1) & 31)
#pragma unroll
    for (int k = 0; k < 16; k++) {
        const int m = tid + k * 512;
        const int sidx = (m & ~63) | ((m & 1) << 5) | ((m >> 1) & 31);
        Ws[sidx] = w4[m];
    }
    __syncthreads();

    const int g = w * SGRID + blockIdx.x;
    if (g >= NG4) return;
    const int t0 = g * 4;

    const unsigned long long pol = mk_policy_el();
    const float* __restrict__ xb = x + (size_t)t0 * D + lane * 8;

    float acc[4][E];
#pragma unroll
    for (int j = 0; j < 4; j++)
#pragma unroll
        for (int e = 0; e < E; e++) acc[j][e] = 0.f;

    unsigned cur[4][8], nxt[4][8];
#pragma unroll
    for (int r = 0; r < 4; r++)
        ldg256_el(xb + r * D, pol, cur[r]);

#pragma unroll 2
    for (int it = 0; it < 16; it++) {
        if (it < 15) {
            const int off = (it + 1) * 256;
#pragma unroll
            for (int r = 0; r < 4; r++)
                ldg256_el(xb + r * D + off, pol, nxt[r]);
        }
        const int wb = it * 64 + lane;
#pragma unroll
        for (int e = 0; e < E; e++) {
            float4 w0 = Ws[e * 1024 + wb];        // cols lane*8 .. +3
            float4 w1 = Ws[e * 1024 + wb + 32];   // cols lane*8+4 .. +7
#pragma unroll
            for (int r = 0; r < 4; r++) {
                acc[r][e] += F(cur[r][0]) * w0.x + F(cur[r][1]) * w0.y
                           + F(cur[r][2]) * w0.z + F(cur[r][3]) * w0.w
                           + F(cur[r][4]) * w1.x + F(cur[r][5]) * w1.y
                           + F(cur[r][6]) * w1.z + F(cur[r][7]) * w1.w;
            }
        }
#pragma unroll
        for (int r = 0; r < 4; r++)
#pragma unroll
            for (int q = 0; q < 8; q++) cur[r][q] = nxt[r][q];
    }

    // warp tree-reduce 32 scalars
#pragma unroll
    for (int off = 16; off > 0; off >>= 1) {
#pragma unroll
        for (int j = 0; j < 4; j++)
#pragma unroll
            for (int e = 0; e < E; e++)
                acc[j][e] += __shfl_xor_sync(0xffffffffu, acc[j][e], off);
    }

    // lanes 0..3 finalize token t0+lane
#pragma unroll
    for (int j = 0; j < 4; j++) {
        if (lane == j) {
            const int t = t0 + j;
            // stable top-2 (first occurrence wins ties, matching jax.lax.top_k)
            float b0 = -3.4e38f, b1 = -3.4e38f;
            int i0 = 0, i1 = 0;
#pragma unroll
            for (int e = 0; e < E; e++) {
                float v = acc[j][e];
                if (v > b0) { b1 = b0; i1 = i0; b0 = v; i0 = e; }
                else if (v > b1) { b1 = v; i1 = e; }
            }
            float ex = expf(b1 - b0);
            float inv = 1.f / (1.f + ex);
            ((int2*)g_exp)[t]    = make_int2(i0, i1);
            ((float2*)g_prob)[t] = make_float2(inv, ex * inv);
        }
    }
}

// ---------------------------------------------------------------------------
// Packed per-expert counters: 8 experts x 8-bit fields across two uints.
// ---------------------------------------------------------------------------
__device__ __forceinline__ void packAdd(int e, unsigned& lo, unsigned& hi) {
    if (e < 4) lo += 1u << (8 * e);
    else       hi += 1u << (8 * (e - 4));
}
__device__ __forceinline__ int fieldOf(unsigned lo, unsigned hi, int e) {
    unsigned v = (e < 4) ? lo : hi;
    return (int)((v >> (8 * (e & 3))) & 0xffu);
}

// ---------------------------------------------------------------------------
// Kernel B: fused rank (hist + global barrier + finalize), 64 blocks x 256.
// ---------------------------------------------------------------------------
__global__ void __launch_bounds__(SPB) rank_kernel(float* __restrict__ out)
{
    __shared__ unsigned wlo[8], whi[8];
    __shared__ int offE[E], totE[E], baseE[E];

    const int b    = blockIdx.x;
    const int tid  = threadIdx.x;
    const int wid  = tid >> 5;
    const int lane = tid & 31;
    const int slot = b * SPB + tid;

    const int e = g_exp[slot];
    unsigned lo = 0, hi = 0;
    packAdd(e, lo, hi);
    const unsigned mlo = lo, mhi = hi;

#pragma unroll
    for (int off = 1; off < 32; off <<= 1) {
        unsigned vlo = __shfl_up_sync(0xffffffffu, lo, off);
        unsigned vhi = __shfl_up_sync(0xffffffffu, hi, off);
        if (lane >= off) { lo += vlo; hi += vhi; }
    }
    if (lane == 31) { wlo[wid] = lo; whi[wid] = hi; }
    __syncthreads();

    unsigned plo = 0, phi = 0;
#pragma unroll
    for (int w2 = 0; w2 < 8; w2++)
        if (w2 < wid) { plo += wlo[w2]; phi += whi[w2]; }

    const int lrank = fieldOf(plo + lo - mlo, phi + hi - mhi, e);

    if (tid < E) {
        unsigned tlo = 0, thi = 0;
#pragma unroll
        for (int w2 = 0; w2 < 8; w2++) { tlo += wlo[w2]; thi += whi[w2]; }
        g_bhist[b * E + tid] = fieldOf(tlo, thi, tid);
    }

    __threadfence();
    __syncthreads();
    if (tid == 0) atomicAdd((int*)&g_sync, 1);
    if (tid == 0) while (g_sync < NHB) { }
    __syncthreads();
    __threadfence();

    if (tid < E) {
        int off = 0, tot = 0;
#pragma unroll
        for (int bb = 0; bb < NHB; bb++) {
            int h = g_bhist[bb * E + tid];
            if (bb < b) off += h;
            tot += h;
        }
        offE[tid] = off; totE[tid] = tot;
    }
    __syncthreads();
    if (tid == 0) {
        int s = 0;
#pragma unroll
        for (int ee = 0; ee < E; ee++) { baseE[ee] = s; s += totE[ee]; }
    }
    __syncthreads();

    const int pos = baseE[e] + offE[e] + lrank;
    g_pos[slot] = pos;
    out[OFF_IDX + pos] = (float)(slot >> 1);   // scatter_indices
    out[OFF_SC  + pos] = g_prob[slot];         // scores_sorted

    if (b == 0 && tid < E) out[OFF_CNT + tid] = (float)totE[tid];

    __syncthreads();
    if (tid == 0) {
        int d = atomicAdd(&g_done, 1);
        if (d == NHB - 1) { g_sync = 0; g_done = 0; }
    }
}

// ---------------------------------------------------------------------------
// Kernel C: scatter copy — read each token row once, write 2 destination rows.
// ---------------------------------------------------------------------------
__global__ void __launch_bounds__(256) scatter_kernel(
    const float* __restrict__ x, float* __restrict__ out)
{
    const int t = blockIdx.x;
    const int p0 = g_pos[2 * t];
    const int p1 = g_pos[2 * t + 1];
    const float4* __restrict__ src = (const float4*)x + (size_t)t * 1024;
    float4* __restrict__ d0 = (float4*)(out + OFF_XG) + (size_t)p0 * 1024;
    float4* __restrict__ d1 = (float4*)(out + OFF_XG) + (size_t)p1 * 1024;

    const int i = threadIdx.x;
    float4 v0 = __ldcs(src + i);
    float4 v1 = __ldcs(src + i + 256);
    float4 v2 = __ldcs(src + i + 512);
    float4 v3 = __ldcs(src + i + 768);
    __stcs(d0 + i,       v0);
    __stcs(d0 + i + 256, v1);
    __stcs(d0 + i + 512, v2);
    __stcs(d0 + i + 768, v3);
    __stcs(d1 + i,       v0);
    __stcs(d1 + i + 256, v1);
    __stcs(d1 + i + 512, v2);
    __stcs(d1 + i + 768, v3);
}

extern "C" void kernel_launch(void* const* d_in, const int* in_sizes, int n_in,
                              void* d_out, int out_size)
{
    const float* x = (const float*)d_in[0];
    const float* W = (const float*)d_in[1];
    if (n_in >= 2 && in_sizes[0] == E * D && in_sizes[1] == (int)((size_t)T * D)) {
        const float* tmp = x; x = W; W = tmp;
    }
    float* out = (float*)d_out;

    static int smem_set = 0;
    if (!smem_set) {
        cudaFuncSetAttribute(router_scores_kernel,
                             cudaFuncAttributeMaxDynamicSharedMemorySize,
                             E * D * (int)sizeof(float));
        smem_set = 1;
    }

    router_scores_kernel<<<SGRID, 512, E * D * sizeof(float)>>>(x, W);
    rank_kernel<<<NHB, SPB>>>(out);
    scatter_kernel<<<T, 256>>>(x, out);
}

// round 15
// speedup vs baseline: 1.0920x; 1.0035x over previous
#include <cuda_runtime.h>
#include <math.h>

#define T 8192
#define D 4096
#define E 8
#define KSEL 2
#define SLOTS (T * KSEL)
#define NHB 64             // hist blocks
#define SPB (SLOTS / NHB)  // 256 slots per hist block
#define NG4 (T / 4)        // 2048 warp-tasks (4 tokens each)
#define SGRID 148
#define XT 8192            // float4 offset of x-tile region in smem
#define SMEM_F4 (XT + 16 * 3 * 128)   // 14336 float4 = 224KB

// Output layout (float32, concatenated in reference-return order)
#define OFF_XG  0
#define OFF_CNT 67108864ll   // 16384*4096
#define OFF_IDX 67108872ll
#define OFF_SC  67125256ll

// Scratch (no allocations allowed -> __device__ globals)
__device__ int   g_exp[SLOTS];
__device__ float g_prob[SLOTS];
__device__ int   g_pos[SLOTS];
__device__ int   g_bhist[NHB * E];
__device__ volatile int g_sync;  // rank kernel global barrier (self-resetting)
__device__ int   g_done;

// L2 evict_last access policy (keeps x resident for the scatter pass)
__device__ __forceinline__ unsigned long long mk_policy_el() {
    unsigned long long p;
    asm("createpolicy.fractional.L2::evict_last.b64 %0, 1.0;" : "=l"(p));
    return p;
}
__device__ __forceinline__ void cp16(unsigned saddr, const float* g,
                                     unsigned long long pol) {
    asm volatile("cp.async.cg.shared.global.L2::cache_hint [%0], [%1], 16, %2;"
                 :: "r"(saddr), "l"(g), "l"(pol));
}

// ---------------------------------------------------------------------------
// Kernel A: router scores + top-2 + softmax.
// grid=148, 512 threads = 16 warps, 4 tokens/warp, task g = w*148 + blk.
// FULL W (128KB) in SMEM + per-warp 3-stage x pipeline via cp.async:
// the async engine keeps 2-3 stages (2KB each) in flight per warp with
// ZERO register cost -> MLP no longer capped by the register file.
// No mainloop barriers (each warp owns its smem ring).
// ---------------------------------------------------------------------------
extern __shared__ float4 Ws[];   // [0,8192): W; [8192,14336): x rings

__global__ void __launch_bounds__(512, 1) router_scores_kernel(
    const float* __restrict__ x, const float* __restrict__ W)
{
    const int tid  = threadIdx.x;
    const int w    = tid >> 5;
    const int lane = tid & 31;

    const float4* __restrict__ w4 = (const float4*)W;

    // stage full W: 8192 float4, 16 per thread, coalesced
#pragma unroll
    for (int k = 0; k < 16; k++) {
        const int idx = tid + k * 512;
        Ws[idx] = w4[idx];
    }
    __syncthreads();

    const int g = w * SGRID + blockIdx.x;
    if (g >= NG4) return;
    const int t0 = g * 4;

    const unsigned long long pol = mk_policy_el();
    const float* __restrict__ xbase = x + (size_t)t0 * D;

    // this warp's 3-stage ring: float4 [slot][row][lane], slot stride 128
    float4* xs = Ws + XT + w * 384;
    const unsigned swarp =
        (unsigned)__cvta_generic_to_shared(xs) + (unsigned)(lane * 16);

    // issue one stage (2KB = 4 rows x 512B) for iteration `it` into `slot`
#define ISSUE(slot, it)                                                    \
    {                                                                      \
        _Pragma("unroll")                                                  \
        for (int q = 0; q < 4; q++) {                                      \
            unsigned sa = swarp + (unsigned)(((slot) * 128 + q * 32) * 16);\
            const float* ga = xbase + q * D + (it) * 128 + lane * 4;       \
            cp16(sa, ga, pol);                                             \
        }                                                                  \
        asm volatile("cp.async.commit_group;");                            \
    }

    ISSUE(0, 0); ISSUE(1, 1); ISSUE(2, 2);

    float acc[4][E];
#pragma unroll
    for (int j = 0; j < 4; j++)
#pragma unroll
        for (int e = 0; e < E; e++) acc[j][e] = 0.f;

    int slot = 0;
    for (int it = 0; it < 32; it++) {
        asm volatile("cp.async.wait_group 2;");

        const float4* st = xs + slot * 128;
        float4 xv0 = st[lane];
        float4 xv1 = st[32 + lane];
        float4 xv2 = st[64 + lane];
        float4 xv3 = st[96 + lane];

        // refill this slot for it+3 (or empty commit to keep group count)
        if (it + 3 < 32) {
            ISSUE(slot, it + 3);
        } else {
            asm volatile("cp.async.commit_group;");
        }

        const int wb = it * 32 + lane;
#pragma unroll
        for (int e = 0; e < E; e++) {
            float4 wv = Ws[e * 1024 + wb];
            acc[0][e] += xv0.x * wv.x + xv0.y * wv.y + xv0.z * wv.z + xv0.w * wv.w;
            acc[1][e] += xv1.x * wv.x + xv1.y * wv.y + xv1.z * wv.z + xv1.w * wv.w;
            acc[2][e] += xv2.x * wv.x + xv2.y * wv.y + xv2.z * wv.z + xv2.w * wv.w;
            acc[3][e] += xv3.x * wv.x + xv3.y * wv.y + xv3.z * wv.z + xv3.w * wv.w;
        }
        slot = (slot == 2) ? 0 : slot + 1;
    }
#undef ISSUE

    // warp tree-reduce 32 scalars
#pragma unroll
    for (int off = 16; off > 0; off >>= 1) {
#pragma unroll
        for (int j = 0; j < 4; j++)
#pragma unroll
            for (int e = 0; e < E; e++)
                acc[j][e] += __shfl_xor_sync(0xffffffffu, acc[j][e], off);
    }

    // lanes 0..3 finalize token t0+lane
#pragma unroll
    for (int j = 0; j < 4; j++) {
        if (lane == j) {
            const int t = t0 + j;
            // stable top-2 (first occurrence wins ties, matching jax.lax.top_k)
            float b0 = -3.4e38f, b1 = -3.4e38f;
            int i0 = 0, i1 = 0;
#pragma unroll
            for (int e = 0; e < E; e++) {
                float v = acc[j][e];
                if (v > b0) { b1 = b0; i1 = i0; b0 = v; i0 = e; }
                else if (v > b1) { b1 = v; i1 = e; }
            }
            float ex = expf(b1 - b0);
            float inv = 1.f / (1.f + ex);
            ((int2*)g_exp)[t]    = make_int2(i0, i1);
            ((float2*)g_prob)[t] = make_float2(inv, ex * inv);
        }
    }
}

// ---------------------------------------------------------------------------
// Packed per-expert counters: 8 experts x 8-bit fields across two uints.
// ---------------------------------------------------------------------------
__device__ __forceinline__ void packAdd(int e, unsigned& lo, unsigned& hi) {
    if (e < 4) lo += 1u << (8 * e);
    else       hi += 1u << (8 * (e - 4));
}
__device__ __forceinline__ int fieldOf(unsigned lo, unsigned hi, int e) {
    unsigned v = (e < 4) ? lo : hi;
    return (int)((v >> (8 * (e & 3))) & 0xffu);
}

// ---------------------------------------------------------------------------
// Kernel B: fused rank (hist + global barrier + finalize), 64 blocks x 256.
// ---------------------------------------------------------------------------
__global__ void __launch_bounds__(SPB) rank_kernel(float* __restrict__ out)
{
    __shared__ unsigned wlo[8], whi[8];
    __shared__ int offE[E], totE[E], baseE[E];

    const int b    = blockIdx.x;
    const int tid  = threadIdx.x;
    const int wid  = tid >> 5;
    const int lane = tid & 31;
    const int slot = b * SPB + tid;

    const int e = g_exp[slot];
    unsigned lo = 0, hi = 0;
    packAdd(e, lo, hi);
    const unsigned mlo = lo, mhi = hi;

#pragma unroll
    for (int off = 1; off < 32; off <<= 1) {
        unsigned vlo = __shfl_up_sync(0xffffffffu, lo, off);
        unsigned vhi = __shfl_up_sync(0xffffffffu, hi, off);
        if (lane >= off) { lo += vlo; hi += vhi; }
    }
    if (lane == 31) { wlo[wid] = lo; whi[wid] = hi; }
    __syncthreads();

    unsigned plo = 0, phi = 0;
#pragma unroll
    for (int w2 = 0; w2 < 8; w2++)
        if (w2 < wid) { plo += wlo[w2]; phi += whi[w2]; }

    const int lrank = fieldOf(plo + lo - mlo, phi + hi - mhi, e);

    if (tid < E) {
        unsigned tlo = 0, thi = 0;
#pragma unroll
        for (int w2 = 0; w2 < 8; w2++) { tlo += wlo[w2]; thi += whi[w2]; }
        g_bhist[b * E + tid] = fieldOf(tlo, thi, tid);
    }

    __threadfence();
    __syncthreads();
    if (tid == 0) atomicAdd((int*)&g_sync, 1);
    if (tid == 0) while (g_sync < NHB) { }
    __syncthreads();
    __threadfence();

    if (tid < E) {
        int off = 0, tot = 0;
#pragma unroll
        for (int bb = 0; bb < NHB; bb++) {
            int h = g_bhist[bb * E + tid];
            if (bb < b) off += h;
            tot += h;
        }
        offE[tid] = off; totE[tid] = tot;
    }
    __syncthreads();
    if (tid == 0) {
        int s = 0;
#pragma unroll
        for (int ee = 0; ee < E; ee++) { baseE[ee] = s; s += totE[ee]; }
    }
    __syncthreads();

    const int pos = baseE[e] + offE[e] + lrank;
    g_pos[slot] = pos;
    out[OFF_IDX + pos] = (float)(slot >> 1);   // scatter_indices
    out[OFF_SC  + pos] = g_prob[slot];         // scores_sorted

    if (b == 0 && tid < E) out[OFF_CNT + tid] = (float)totE[tid];

    __syncthreads();
    if (tid == 0) {
        int d = atomicAdd(&g_done, 1);
        if (d == NHB - 1) { g_sync = 0; g_done = 0; }
    }
}

// ---------------------------------------------------------------------------
// Kernel C: scatter copy — read each token row once, write 2 destination rows.
// ---------------------------------------------------------------------------
__global__ void __launch_bounds__(256) scatter_kernel(
    const float* __restrict__ x, float* __restrict__ out)
{
    const int t = blockIdx.x;
    const int p0 = g_pos[2 * t];
    const int p1 = g_pos[2 * t + 1];
    const float4* __restrict__ src = (const float4*)x + (size_t)t * 1024;
    float4* __restrict__ d0 = (float4*)(out + OFF_XG) + (size_t)p0 * 1024;
    float4* __restrict__ d1 = (float4*)(out + OFF_XG) + (size_t)p1 * 1024;

    const int i = threadIdx.x;
    float4 v0 = __ldcs(src + i);
    float4 v1 = __ldcs(src + i + 256);
    float4 v2 = __ldcs(src + i + 512);
    float4 v3 = __ldcs(src + i + 768);
    __stcs(d0 + i,       v0);
    __stcs(d0 + i + 256, v1);
    __stcs(d0 + i + 512, v2);
    __stcs(d0 + i + 768, v3);
    __stcs(d1 + i,       v0);
    __stcs(d1 + i + 256, v1);
    __stcs(d1 + i + 512, v2);
    __stcs(d1 + i + 768, v3);
}

extern "C" void kernel_launch(void* const* d_in, const int* in_sizes, int n_in,
                              void* d_out, int out_size)
{
    const float* x = (const float*)d_in[0];
    const float* W = (const float*)d_in[1];
    if (n_in >= 2 && in_sizes[0] == E * D && in_sizes[1] == (int)((size_t)T * D)) {
        const float* tmp = x; x = W; W = tmp;
    }
    float* out = (float*)d_out;

    static int smem_set = 0;
    if (!smem_set) {
        cudaFuncSetAttribute(router_scores_kernel,
                             cudaFuncAttributeMaxDynamicSharedMemorySize,
                             SMEM_F4 * (int)sizeof(float4));
        smem_set = 1;
    }

    router_scores_kernel<<<SGRID, 512, SMEM_F4 * sizeof(float4)>>>(x, W);
    rank_kernel<<<NHB, SPB>>>(out);
    scatter_kernel<<<T, 256>>>(x, out);
}